// round 8
// baseline (speedup 1.0000x reference)
#include <cuda_runtime.h>
#include <math.h>

#define NB    8192
#define ND    32
#define NK    64
#define NSTEP 255
#define TPB   224        // 7 warps
#define NW    7
#define SW    8          // samples per warp
#define NBLK  148        // 148 * 56 = 8288 slots >= 8192
#define TS4   17         // table row stride in float4 (272B -> conflict-free)

typedef unsigned long long u64;

__device__ __forceinline__ void upk2(u64 v, float& lo, float& hi) {
    asm("mov.b64 {%0, %1}, %2;" : "=f"(lo), "=f"(hi) : "l"(v));
}
__device__ __forceinline__ u64 add2(u64 a, u64 b) {
    u64 d; asm("add.rn.f32x2 %0, %1, %2;" : "=l"(d) : "l"(a), "l"(b)); return d;
}
__device__ __forceinline__ u64 fma2_(u64 a, u64 b, u64 c) {
    u64 d; asm("fma.rn.f32x2 %0, %1, %2, %3;" : "=l"(d) : "l"(a), "l"(b), "l"(c)); return d;
}

__device__ __forceinline__ float upd1(float x, float P, float Q,
                                      float invS, float hb, float sn, float z) {
    // score = (2xP + Q)/S ; c = 0.5x + score ; x += hb*c + sn*z
    float tx = x + x;
    float u  = fmaf(tx, P, Q);
    float c  = fmaf(invS, u, 0.5f * x);
    return fmaf(sn, z, fmaf(hb, c, x));
}

__global__ __launch_bounds__(TPB, 1)
void sbm_kernel(const float* __restrict__ x_init,
                const float* __restrict__ centers,
                const float* __restrict__ stds,
                const float* __restrict__ weights,
                const float* __restrict__ noise,
                float* __restrict__ out)
{
    // table row k: 16 float4 chunks { ivh[2c], ivh[2c+1], am[2c], am[2c+1] }
    // ivh = -0.5/v,  am = m/v
    __shared__ float4 sm_tab[NK * TS4];              // 17408 B
    __shared__ float  sm_c  [NK];                    // 256 B
    __shared__ float4 sm_wq [NW][NK][2];             // 14336 B: quad w {ws,ws,ws',ws'}
    __shared__ float  sm_x  [NW][SW][ND];            // 7168 B

    const int tid  = threadIdx.x;
    const int lane = tid & 31;
    const int wid  = tid >> 5;
    const int p    = lane & 15;       // dim pair 0..15
    const int h    = lane >> 4;       // k-half 0/1
    const int d0   = p * 2;

    const int sbase = blockIdx.x * (NW * SW) + wid * SW;

    // init per-warp x slab (each lane: its pair, 4 samples of its half)
    #pragma unroll
    for (int jj = 0; jj < 4; jj++) {
        int s  = h * 4 + jj;
        int cs = min(sbase + s, NB - 1);
        *reinterpret_cast<float2*>(&sm_x[wid][s][d0]) =
            *reinterpret_cast<const float2*>(x_init + (size_t)cs * ND + d0);
    }

    const float T_MAX = 1.0f;
    const float T_MIN = 1e-4f;
    const float H   = (T_MAX - T_MIN) / 255.0f;
    const float SQH = sqrtf(H);

    for (int i = 0; i < NSTEP; i++) {
        float t  = T_MAX - (float)i * H;
        float bt = 0.1f + 19.9f * t;
        float Bt = 0.1f * t + 9.95f * t * t;
        float eB = expf(-Bt);
        float om = 1.0f - eB;
        float sq = sqrtf(eB);
        float hb = H * bt;
        float sn = sqrtf(bt) * SQH;

        __syncthreads();   // table readers of prev step done; x slab visible

        // ---- build table (threads 0..127: k = tid/2, half of dims) ----
        if (tid < 128) {
            int k = tid >> 1;
            int hh = (tid & 1) * 16;
            float lsum = 0.0f, qsum = 0.0f;
            #pragma unroll
            for (int jj = 0; jj < 4; jj++) {
                int d = hh + jj * 4;
                float4 c4 = *reinterpret_cast<const float4*>(centers + k * ND + d);
                float4 s4 = *reinterpret_cast<const float4*>(stds    + k * ND + d);
                float v0 = eB * s4.x * s4.x + om;
                float v1 = eB * s4.y * s4.y + om;
                float v2 = eB * s4.z * s4.z + om;
                float v3 = eB * s4.w * s4.w + om;
                float i0 = 1.0f / v0, i1 = 1.0f / v1, i2 = 1.0f / v2, i3 = 1.0f / v3;
                float m0 = sq * c4.x, m1 = sq * c4.y, m2 = sq * c4.z, m3 = sq * c4.w;
                float a0 = m0 * i0, a1 = m1 * i1, a2 = m2 * i2, a3 = m3 * i3;
                sm_tab[k * TS4 + (d >> 1)    ] = make_float4(-0.5f*i0, -0.5f*i1, a0, a1);
                sm_tab[k * TS4 + (d >> 1) + 1] = make_float4(-0.5f*i2, -0.5f*i3, a2, a3);
                qsum += a0*m0 + a1*m1 + a2*m2 + a3*m3;
                const float TWO_PI = 6.2831853071795864f;
                lsum += __logf(TWO_PI*v0) + __logf(TWO_PI*v1)
                      + __logf(TWO_PI*v2) + __logf(TWO_PI*v3);
            }
            lsum += __shfl_xor_sync(0xffffffffu, lsum, 1);
            qsum += __shfl_xor_sync(0xffffffffu, qsum, 1);
            if ((tid & 1) == 0) {
                sm_c[k] = fmaf(-16.0f, lsum, fmaf(-0.5f, qsum, __logf(weights[k])));
            }
        }
        __syncthreads();

        // ---- pass 1: logc for 2 k per lane x 8 samples (row resident in regs) ----
        float lc0[SW], lc1[SW];
        #define PASS1(KIDX, LC)                                                        \
        {                                                                              \
            int k = (KIDX);                                                            \
            u64 riv[16], ram[16];                                                      \
            const ulonglong2* tp = reinterpret_cast<const ulonglong2*>(&sm_tab[k*TS4]);\
            _Pragma("unroll")                                                          \
            for (int c = 0; c < 16; c++) { ulonglong2 v = tp[c]; riv[c]=v.x; ram[c]=v.y; } \
            float cK = sm_c[k];                                                        \
            _Pragma("unroll")                                                          \
            for (int s = 0; s < SW; s++) {                                             \
                const ulonglong2* xp = reinterpret_cast<const ulonglong2*>(&sm_x[wid][s][0]); \
                u64 a0 = 0ull, a1 = 0ull;                                              \
                _Pragma("unroll")                                                      \
                for (int c2 = 0; c2 < 8; c2++) {                                       \
                    ulonglong2 xv = xp[c2];                                            \
                    u64 t0 = fma2_(riv[2*c2],   xv.x, ram[2*c2]);                      \
                    a0 = fma2_(t0, xv.x, a0);                                          \
                    u64 t1 = fma2_(riv[2*c2+1], xv.y, ram[2*c2+1]);                    \
                    a1 = fma2_(t1, xv.y, a1);                                          \
                }                                                                      \
                float lo, hi; upk2(add2(a0, a1), lo, hi);                              \
                LC[s] = (lo + hi) + cK;                                                \
            }                                                                          \
        }
        PASS1(lane,      lc0)
        PASS1(lane + 32, lc1)
        #undef PASS1

        // ---- softmax stats per sample (reduce over 32 k-lanes) ----
        float S[SW], w0[SW], w1[SW];
        #pragma unroll
        for (int s = 0; s < SW; s++) {
            float m = fmaxf(lc0[s], lc1[s]);
            #pragma unroll
            for (int r = 1; r <= 16; r <<= 1)
                m = fmaxf(m, __shfl_xor_sync(0xffffffffu, m, r));
            float a = __expf(lc0[s] - m);
            float b = __expf(lc1[s] - m);
            w0[s] = a; w1[s] = b;
            float ss = a + b;
            #pragma unroll
            for (int r = 1; r <= 16; r <<= 1)
                ss += __shfl_xor_sync(0xffffffffu, ss, r);
            S[s] = ss;
        }

        // ---- pass 2 in two sample-quads (shared duplicated-w buffer) ----
        #pragma unroll
        for (int q = 0; q < 2; q++) {
            // store duplicated w for this quad: lane's two k rows
            sm_wq[wid][lane][0]      = make_float4(w0[4*q  ], w0[4*q  ], w0[4*q+1], w0[4*q+1]);
            sm_wq[wid][lane][1]      = make_float4(w0[4*q+2], w0[4*q+2], w0[4*q+3], w0[4*q+3]);
            sm_wq[wid][lane + 32][0] = make_float4(w1[4*q  ], w1[4*q  ], w1[4*q+1], w1[4*q+1]);
            sm_wq[wid][lane + 32][1] = make_float4(w1[4*q+2], w1[4*q+2], w1[4*q+3], w1[4*q+3]);
            __syncwarp();

            u64 P[4], Q[4];
            #pragma unroll
            for (int j = 0; j < 4; j++) { P[j] = 0ull; Q[j] = 0ull; }

            const int kb = h * 32;
            #pragma unroll 4
            for (int kk = 0; kk < 32; kk++) {
                int k = kb + kk;
                ulonglong2 tv = *reinterpret_cast<const ulonglong2*>(&sm_tab[k*TS4 + p]);
                ulonglong2 wA = *reinterpret_cast<const ulonglong2*>(&sm_wq[wid][k][0]);
                ulonglong2 wB = *reinterpret_cast<const ulonglong2*>(&sm_wq[wid][k][1]);
                P[0] = fma2_(wA.x, tv.x, P[0]);  Q[0] = fma2_(wA.x, tv.y, Q[0]);
                P[1] = fma2_(wA.y, tv.x, P[1]);  Q[1] = fma2_(wA.y, tv.y, Q[1]);
                P[2] = fma2_(wB.x, tv.x, P[2]);  Q[2] = fma2_(wB.x, tv.y, Q[2]);
                P[3] = fma2_(wB.y, tv.x, P[3]);  Q[3] = fma2_(wB.y, tv.y, Q[3]);
            }
            // merge the two k-halves
            #pragma unroll
            for (int j = 0; j < 4; j++) {
                P[j] = add2(P[j], __shfl_xor_sync(0xffffffffu, P[j], 16));
                Q[j] = add2(Q[j], __shfl_xor_sync(0xffffffffu, Q[j], 16));
            }

            // update this quad (all lanes update their pair for all 4 samples;
            // both k-halves hold identical P,Q -> benign duplicate writes)
            #pragma unroll
            for (int j = 0; j < 4; j++) {
                int s  = 4 * q + j;
                int cs = min(sbase + s, NB - 1);
                float invS = 1.0f / S[s];
                float2 z = *reinterpret_cast<const float2*>(
                    noise + ((size_t)i * NB + (size_t)cs) * ND + d0);
                float2 xo = *reinterpret_cast<float2*>(&sm_x[wid][s][d0]);
                float pa, pb, qa, qb;
                upk2(P[j], pa, pb);
                upk2(Q[j], qa, qb);
                xo.x = upd1(xo.x, pa, qa, invS, hb, sn, z.x);
                xo.y = upd1(xo.y, pb, qb, invS, hb, sn, z.y);
                *reinterpret_cast<float2*>(&sm_x[wid][s][d0]) = xo;
            }
            __syncwarp();
        }
    }

    // ---- final store (h==0 lanes store all 8 samples' pairs) ----
    if (h == 0) {
        #pragma unroll
        for (int s = 0; s < SW; s++) {
            int sr = sbase + s;
            if (sr < NB) {
                *reinterpret_cast<float2*>(out + (size_t)sr * ND + d0) =
                    *reinterpret_cast<const float2*>(&sm_x[wid][s][d0]);
            }
        }
    }
}

extern "C" void kernel_launch(void* const* d_in, const int* in_sizes, int n_in,
                              void* d_out, int out_size)
{
    const float* x_init  = (const float*)d_in[0];
    const float* centers = (const float*)d_in[1];
    const float* stds    = (const float*)d_in[2];
    const float* weights = (const float*)d_in[3];
    const float* noise   = (const float*)d_in[4];
    float* out = (float*)d_out;

    sbm_kernel<<<NBLK, TPB>>>(x_init, centers, stds, weights, noise, out);
}

// round 9
// speedup vs baseline: 1.5890x; 1.5890x over previous
#include <cuda_runtime.h>
#include <math.h>

#define NB    8192
#define ND    32
#define NK    64
#define NSTEP 255
#define TPB   128        // 4 warps
#define NWRP  4
#define SW    7          // samples per warp
#define SPB   28         // samples per block
#define NBLK  296        // 296*28 = 8288 slots >= 8192 ; 2 blocks/SM
#define TS4   17         // table row stride in float4
#define WROW  14         // floats per w row (7 duplicated pairs)

typedef unsigned long long u64;

__device__ __forceinline__ void upk2(u64 v, float& lo, float& hi) {
    asm("mov.b64 {%0, %1}, %2;" : "=f"(lo), "=f"(hi) : "l"(v));
}
__device__ __forceinline__ u64 add2(u64 a, u64 b) {
    u64 d; asm("add.rn.f32x2 %0, %1, %2;" : "=l"(d) : "l"(a), "l"(b)); return d;
}
__device__ __forceinline__ u64 fma2_(u64 a, u64 b, u64 c) {
    u64 d; asm("fma.rn.f32x2 %0, %1, %2, %3;" : "=l"(d) : "l"(a), "l"(b), "l"(c)); return d;
}

__device__ __forceinline__ float upd1(float x, float P, float Q,
                                      float invS, float hb, float sn, float z) {
    // score = (2xP + Q)/S ;  c = 0.5x + score ;  x += hb*c + sn*z
    float tx = x + x;
    float u  = fmaf(tx, P, Q);
    float c  = fmaf(invS, u, 0.5f * x);
    return fmaf(sn, z, fmaf(hb, c, x));
}

__global__ __launch_bounds__(TPB, 2)
void sbm_kernel(const float* __restrict__ x_init,
                const float* __restrict__ centers,
                const float* __restrict__ stds,
                const float* __restrict__ weights,
                const float* __restrict__ noise,
                float* __restrict__ out)
{
    // table row k: 16 chunks (float4) { ivh[2c], ivh[2c+1], am[2c], am[2c+1] }
    // ivh = -0.5/v ; am = m/v
    __shared__ float4 sm_tab[NK * TS4];          // 17408 B
    __shared__ float  sm_c  [NK];                // 256 B
    __shared__ float  sm_w  [NWRP * NK * WROW];  // 14336 B, rows interleaved by k-half
    __shared__ float  sm_x  [NWRP][SW][ND];      // 3584 B

    const int tid  = threadIdx.x;
    const int lane = tid & 31;
    const int wid  = tid >> 5;
    const int p    = lane & 15;        // dim pair (pass 2 / update)
    const int h    = lane >> 4;        // k-half  (pass 2 / update)

    const int sbase = blockIdx.x * SPB + wid * SW;

    // ---- init x slab: lane (p,h) loads its pair for its sample subset ----
    #pragma unroll
    for (int j = 0; j < 4; j++) {
        int s = h * 4 + j;
        if (s < SW) {
            int cs = min(sbase + s, NB - 1);
            *reinterpret_cast<float2*>(&sm_x[wid][s][2*p]) =
                *reinterpret_cast<const float2*>(x_init + (size_t)cs * ND + 2*p);
        }
    }

    const float T_MAX = 1.0f;
    const float T_MIN = 1e-4f;
    const float H   = (T_MAX - T_MIN) / 255.0f;
    const float SQH = sqrtf(H);

    for (int i = 0; i < NSTEP; i++) {
        float t  = T_MAX - (float)i * H;
        float bt = 0.1f + 19.9f * t;
        float Bt = 0.1f * t + 9.95f * t * t;
        float eB = expf(-Bt);
        float om = 1.0f - eB;
        float sq = sqrtf(eB);
        float hb = H * bt;
        float sn = sqrtf(bt) * SQH;

        __syncthreads();   // prev step's table readers done; x slab visible

        // ---- build table: all 128 threads, k = tid/2, half of dims ----
        {
            int k  = tid >> 1;
            int hh = (tid & 1) * 16;
            float lsum = 0.0f, qsum = 0.0f;
            #pragma unroll
            for (int jj = 0; jj < 4; jj++) {
                int d = hh + jj * 4;
                float4 c4 = *reinterpret_cast<const float4*>(centers + k * ND + d);
                float4 s4 = *reinterpret_cast<const float4*>(stds    + k * ND + d);
                float v0 = eB * s4.x * s4.x + om;
                float v1 = eB * s4.y * s4.y + om;
                float v2 = eB * s4.z * s4.z + om;
                float v3 = eB * s4.w * s4.w + om;
                float i0 = 1.0f / v0, i1 = 1.0f / v1, i2 = 1.0f / v2, i3 = 1.0f / v3;
                float m0 = sq * c4.x, m1 = sq * c4.y, m2 = sq * c4.z, m3 = sq * c4.w;
                float a0 = m0 * i0, a1 = m1 * i1, a2 = m2 * i2, a3 = m3 * i3;
                sm_tab[k * TS4 + (d >> 1)    ] = make_float4(-0.5f*i0, -0.5f*i1, a0, a1);
                sm_tab[k * TS4 + (d >> 1) + 1] = make_float4(-0.5f*i2, -0.5f*i3, a2, a3);
                qsum += a0*m0 + a1*m1 + a2*m2 + a3*m3;
                const float TWO_PI = 6.2831853071795864f;
                lsum += __logf(TWO_PI*v0) + __logf(TWO_PI*v1)
                      + __logf(TWO_PI*v2) + __logf(TWO_PI*v3);
            }
            lsum += __shfl_xor_sync(0xffffffffu, lsum, 1);
            qsum += __shfl_xor_sync(0xffffffffu, qsum, 1);
            if ((tid & 1) == 0) {
                sm_c[k] = fmaf(-16.0f, lsum, fmaf(-0.5f, qsum, __logf(weights[k])));
            }
        }
        __syncthreads();

        // ---- pass 1: chunk-outer; lane owns k = lane, lane+32 ----
        u64 acc0[SW], acc1[SW];
        #pragma unroll
        for (int s = 0; s < SW; s++) { acc0[s] = 0ull; acc1[s] = 0ull; }

        const float4* t0p = &sm_tab[lane * TS4];
        const float4* t1p = &sm_tab[(lane + 32) * TS4];
        #pragma unroll 4
        for (int c = 0; c < 16; c++) {
            ulonglong2 ta = *reinterpret_cast<const ulonglong2*>(t0p + c);
            ulonglong2 tb = *reinterpret_cast<const ulonglong2*>(t1p + c);
            #pragma unroll
            for (int s = 0; s < SW; s++) {
                u64 xv = *reinterpret_cast<const u64*>(&sm_x[wid][s][2*c]);
                acc0[s] = fma2_(fma2_(ta.x, xv, ta.y), xv, acc0[s]);
                acc1[s] = fma2_(fma2_(tb.x, xv, tb.y), xv, acc1[s]);
            }
        }

        // ---- softmax stats (reduce over full warp = 64 k) ----
        float cA = sm_c[lane], cB = sm_c[lane + 32];
        float w0[SW], w1[SW], S[SW];
        #pragma unroll
        for (int s = 0; s < SW; s++) {
            float lo, hi;
            upk2(acc0[s], lo, hi);  float lc0 = (lo + hi) + cA;
            upk2(acc1[s], lo, hi);  float lc1 = (lo + hi) + cB;
            float m = fmaxf(lc0, lc1);
            #pragma unroll
            for (int r = 1; r <= 16; r <<= 1)
                m = fmaxf(m, __shfl_xor_sync(0xffffffffu, m, r));
            float a = __expf(lc0 - m);
            float b = __expf(lc1 - m);
            w0[s] = a; w1[s] = b;
            float ss = a + b;
            #pragma unroll
            for (int r = 1; r <= 16; r <<= 1)
                ss += __shfl_xor_sync(0xffffffffu, ss, r);
            S[s] = ss;
        }

        // ---- store duplicated w pairs; rows 2*lane (k=lane), 2*lane+1 (k=lane+32)
        {
            float4* wb = reinterpret_cast<float4*>(
                sm_w + wid * (NK * WROW) + lane * (2 * WROW));
            wb[0] = make_float4(w0[0], w0[0], w0[1], w0[1]);
            wb[1] = make_float4(w0[2], w0[2], w0[3], w0[3]);
            wb[2] = make_float4(w0[4], w0[4], w0[5], w0[5]);
            wb[3] = make_float4(w0[6], w0[6], w1[0], w1[0]);
            wb[4] = make_float4(w1[1], w1[1], w1[2], w1[2]);
            wb[5] = make_float4(w1[3], w1[3], w1[4], w1[4]);
            wb[6] = make_float4(w1[5], w1[5], w1[6], w1[6]);
        }
        __syncwarp();

        // ---- pass 2: lane (p,h) streams k = kk + 32h, accumulates P,Q for pair p
        u64 P[SW], Q[SW];
        #pragma unroll
        for (int s = 0; s < SW; s++) { P[s] = 0ull; Q[s] = 0ull; }

        const float* wbase = sm_w + wid * (NK * WROW) + h * WROW;  // row 2kk+h
        #pragma unroll 2
        for (int kk = 0; kk < 32; kk++) {
            ulonglong2 tv = *reinterpret_cast<const ulonglong2*>(
                &sm_tab[(kk + 32 * h) * TS4 + p]);
            const u64* wr = reinterpret_cast<const u64*>(wbase + kk * (2 * WROW));
            #pragma unroll
            for (int s = 0; s < SW; s++) {
                u64 wv = wr[s];
                P[s] = fma2_(wv, tv.x, P[s]);
                Q[s] = fma2_(wv, tv.y, Q[s]);
            }
        }
        // merge the two k-halves
        #pragma unroll
        for (int s = 0; s < SW; s++) {
            P[s] = add2(P[s], __shfl_xor_sync(0xffffffffu, P[s], 16));
            Q[s] = add2(Q[s], __shfl_xor_sync(0xffffffffu, Q[s], 16));
        }

        // ---- Euler-Maruyama update: h=0 -> s=0..3, h=1 -> s=4..6 ----
        #pragma unroll
        for (int j = 0; j < 4; j++) {
            int s = h * 4 + j;
            if (s < SW) {
                int cs = min(sbase + s, NB - 1);
                float invS = 1.0f / S[s];
                float2 z = *reinterpret_cast<const float2*>(
                    noise + ((size_t)i * NB + (size_t)cs) * ND + 2*p);
                float2 xo = *reinterpret_cast<float2*>(&sm_x[wid][s][2*p]);
                float pa, pb, qa, qb;
                upk2(P[s], pa, pb);
                upk2(Q[s], qa, qb);
                xo.x = upd1(xo.x, pa, qa, invS, hb, sn, z.x);
                xo.y = upd1(xo.y, pb, qb, invS, hb, sn, z.y);
                *reinterpret_cast<float2*>(&sm_x[wid][s][2*p]) = xo;
            }
        }
        // next-step readers wait at loop-top __syncthreads
    }

    // ---- final store ----
    #pragma unroll
    for (int j = 0; j < 4; j++) {
        int s = h * 4 + j;
        if (s < SW) {
            int r = sbase + s;
            if (r < NB) {
                *reinterpret_cast<float2*>(out + (size_t)r * ND + 2*p) =
                    *reinterpret_cast<const float2*>(&sm_x[wid][s][2*p]);
            }
        }
    }
}

extern "C" void kernel_launch(void* const* d_in, const int* in_sizes, int n_in,
                              void* d_out, int out_size)
{
    const float* x_init  = (const float*)d_in[0];
    const float* centers = (const float*)d_in[1];
    const float* stds    = (const float*)d_in[2];
    const float* weights = (const float*)d_in[3];
    const float* noise   = (const float*)d_in[4];
    float* out = (float*)d_out;

    sbm_kernel<<<NBLK, TPB>>>(x_init, centers, stds, weights, noise, out);
}

// round 10
// speedup vs baseline: 1.7386x; 1.0942x over previous
#include <cuda_runtime.h>
#include <math.h>

#define NB    8192
#define ND    32
#define NK    64
#define NSTEP 255
#define TPB   128        // 4 warps
#define NWRP  4
#define SW    5          // samples per warp
#define SPB   20         // samples per block
#define NBLK  444        // 3 blocks/SM x 148 SMs, uniform; 444*20 = 8880 slots
#define TS4   17         // table row stride in float4
#define WROW  12         // floats per w row: 6 dup-pairs (5 used + pad), 48B

typedef unsigned long long u64;

__device__ __forceinline__ void upk2(u64 v, float& lo, float& hi) {
    asm("mov.b64 {%0, %1}, %2;" : "=f"(lo), "=f"(hi) : "l"(v));
}
__device__ __forceinline__ u64 add2(u64 a, u64 b) {
    u64 d; asm("add.rn.f32x2 %0, %1, %2;" : "=l"(d) : "l"(a), "l"(b)); return d;
}
__device__ __forceinline__ u64 fma2_(u64 a, u64 b, u64 c) {
    u64 d; asm("fma.rn.f32x2 %0, %1, %2, %3;" : "=l"(d) : "l"(a), "l"(b), "l"(c)); return d;
}

__device__ __forceinline__ float upd1(float x, float P, float Q,
                                      float invS, float hb, float sn, float z) {
    // score = (2xP + Q)/S ;  c = 0.5x + score ;  x += hb*c + sn*z
    float tx = x + x;
    float u  = fmaf(tx, P, Q);
    float c  = fmaf(invS, u, 0.5f * x);
    return fmaf(sn, z, fmaf(hb, c, x));
}

__global__ __launch_bounds__(TPB, 3)
void sbm_kernel(const float* __restrict__ x_init,
                const float* __restrict__ centers,
                const float* __restrict__ stds,
                const float* __restrict__ weights,
                const float* __restrict__ noise,
                float* __restrict__ out)
{
    // table row k: 16 chunks (float4) { ivh[2c], ivh[2c+1], am[2c], am[2c+1] }
    // ivh = -0.5/v ; am = m/v
    __shared__ float4 sm_tab[NK * TS4];            // 17408 B
    __shared__ float  sm_c  [NK];                  // 256 B
    __shared__ float  sm_w  [NWRP * NK * WROW];    // 12288 B, rows interleaved (2k+h)
    __shared__ float  sm_x  [NWRP][SW][ND];        // 2560 B

    const int tid  = threadIdx.x;
    const int lane = tid & 31;
    const int wid  = tid >> 5;
    const int p    = lane & 15;        // dim pair (pass 2 / update)
    const int h    = lane >> 4;        // k-half  (pass 2 / update)

    const int sbase = blockIdx.x * SPB + wid * SW;

    // ---- init x slab: lanes cover (pair p) x (samples split by h) ----
    #pragma unroll
    for (int j = 0; j < 3; j++) {
        int s = h * 3 + j;
        if (s < SW) {
            int cs = min(sbase + s, NB - 1);
            *reinterpret_cast<float2*>(&sm_x[wid][s][2*p]) =
                *reinterpret_cast<const float2*>(x_init + (size_t)cs * ND + 2*p);
        }
    }

    const float T_MAX = 1.0f;
    const float T_MIN = 1e-4f;
    const float H   = (T_MAX - T_MIN) / 255.0f;
    const float SQH = sqrtf(H);

    for (int i = 0; i < NSTEP; i++) {
        float t  = T_MAX - (float)i * H;
        float bt = 0.1f + 19.9f * t;
        float Bt = 0.1f * t + 9.95f * t * t;
        float eB = expf(-Bt);
        float om = 1.0f - eB;
        float sq = sqrtf(eB);
        float hb = H * bt;
        float sn = sqrtf(bt) * SQH;

        __syncthreads();   // prev step's table readers done; x slab visible

        // ---- build table: all 128 threads, k = tid/2, half of dims ----
        {
            int k  = tid >> 1;
            int hh = (tid & 1) * 16;
            float lsum = 0.0f, qsum = 0.0f;
            #pragma unroll
            for (int jj = 0; jj < 4; jj++) {
                int d = hh + jj * 4;
                float4 c4 = *reinterpret_cast<const float4*>(centers + k * ND + d);
                float4 s4 = *reinterpret_cast<const float4*>(stds    + k * ND + d);
                float v0 = eB * s4.x * s4.x + om;
                float v1 = eB * s4.y * s4.y + om;
                float v2 = eB * s4.z * s4.z + om;
                float v3 = eB * s4.w * s4.w + om;
                float i0 = 1.0f / v0, i1 = 1.0f / v1, i2 = 1.0f / v2, i3 = 1.0f / v3;
                float m0 = sq * c4.x, m1 = sq * c4.y, m2 = sq * c4.z, m3 = sq * c4.w;
                float a0 = m0 * i0, a1 = m1 * i1, a2 = m2 * i2, a3 = m3 * i3;
                sm_tab[k * TS4 + (d >> 1)    ] = make_float4(-0.5f*i0, -0.5f*i1, a0, a1);
                sm_tab[k * TS4 + (d >> 1) + 1] = make_float4(-0.5f*i2, -0.5f*i3, a2, a3);
                qsum += a0*m0 + a1*m1 + a2*m2 + a3*m3;
                const float TWO_PI = 6.2831853071795864f;
                lsum += __logf(TWO_PI*v0) + __logf(TWO_PI*v1)
                      + __logf(TWO_PI*v2) + __logf(TWO_PI*v3);
            }
            lsum += __shfl_xor_sync(0xffffffffu, lsum, 1);
            qsum += __shfl_xor_sync(0xffffffffu, qsum, 1);
            if ((tid & 1) == 0) {
                sm_c[k] = fmaf(-16.0f, lsum, fmaf(-0.5f, qsum, __logf(weights[k])));
            }
        }
        __syncthreads();

        // ---- pass 1: lane owns k = lane, lane+32; chunk-pair outer ----
        u64 acc0[SW], acc1[SW];
        #pragma unroll
        for (int s = 0; s < SW; s++) { acc0[s] = 0ull; acc1[s] = 0ull; }

        const ulonglong2* t0p = reinterpret_cast<const ulonglong2*>(&sm_tab[lane * TS4]);
        const ulonglong2* t1p = reinterpret_cast<const ulonglong2*>(&sm_tab[(lane + 32) * TS4]);
        #pragma unroll
        for (int c2 = 0; c2 < 8; c2++) {
            ulonglong2 ta0 = t0p[2*c2], ta1 = t0p[2*c2 + 1];
            ulonglong2 tb0 = t1p[2*c2], tb1 = t1p[2*c2 + 1];
            #pragma unroll
            for (int s = 0; s < SW; s++) {
                ulonglong2 xv = *reinterpret_cast<const ulonglong2*>(&sm_x[wid][s][4*c2]);
                acc0[s] = fma2_(fma2_(ta0.x, xv.x, ta0.y), xv.x, acc0[s]);
                acc0[s] = fma2_(fma2_(ta1.x, xv.y, ta1.y), xv.y, acc0[s]);
                acc1[s] = fma2_(fma2_(tb0.x, xv.x, tb0.y), xv.x, acc1[s]);
                acc1[s] = fma2_(fma2_(tb1.x, xv.y, tb1.y), xv.y, acc1[s]);
            }
        }

        // ---- softmax stats (reduce over full warp = 64 k) ----
        float cA = sm_c[lane], cB = sm_c[lane + 32];
        float w0[SW], w1[SW], S[SW];
        #pragma unroll
        for (int s = 0; s < SW; s++) {
            float lo, hi;
            upk2(acc0[s], lo, hi);  float lc0 = (lo + hi) + cA;
            upk2(acc1[s], lo, hi);  float lc1 = (lo + hi) + cB;
            float m = fmaxf(lc0, lc1);
            #pragma unroll
            for (int r = 1; r <= 16; r <<= 1)
                m = fmaxf(m, __shfl_xor_sync(0xffffffffu, m, r));
            float a = __expf(lc0 - m);
            float b = __expf(lc1 - m);
            w0[s] = a; w1[s] = b;
            float ss = a + b;
            #pragma unroll
            for (int r = 1; r <= 16; r <<= 1)
                ss += __shfl_xor_sync(0xffffffffu, ss, r);
            S[s] = ss;
        }

        // ---- store duplicated w pairs: row 2*lane <- k=lane, row 2*lane+1 <- k=lane+32
        {
            float4* wb = reinterpret_cast<float4*>(
                sm_w + wid * (NK * WROW) + lane * (2 * WROW));
            wb[0] = make_float4(w0[0], w0[0], w0[1], w0[1]);
            wb[1] = make_float4(w0[2], w0[2], w0[3], w0[3]);
            wb[2] = make_float4(w0[4], w0[4], 0.0f, 0.0f);
            wb[3] = make_float4(w1[0], w1[0], w1[1], w1[1]);
            wb[4] = make_float4(w1[2], w1[2], w1[3], w1[3]);
            wb[5] = make_float4(w1[4], w1[4], 0.0f, 0.0f);
        }
        __syncwarp();

        // ---- pass 2: lane (p,h) streams k = kk + 32h, P,Q for dim pair p ----
        u64 P[SW], Q[SW];
        #pragma unroll
        for (int s = 0; s < SW; s++) { P[s] = 0ull; Q[s] = 0ull; }

        const float* wbase = sm_w + wid * (NK * WROW) + h * WROW;   // row 2kk+h
        #pragma unroll 4
        for (int kk = 0; kk < 32; kk++) {
            ulonglong2 tv = *reinterpret_cast<const ulonglong2*>(
                &sm_tab[(kk + 32 * h) * TS4 + p]);
            const float* wr = wbase + kk * (2 * WROW);
            ulonglong2 wA = *reinterpret_cast<const ulonglong2*>(wr);      // s0,s1
            ulonglong2 wB = *reinterpret_cast<const ulonglong2*>(wr + 4);  // s2,s3
            u64        wC = *reinterpret_cast<const u64*>(wr + 8);         // s4
            P[0] = fma2_(wA.x, tv.x, P[0]);  Q[0] = fma2_(wA.x, tv.y, Q[0]);
            P[1] = fma2_(wA.y, tv.x, P[1]);  Q[1] = fma2_(wA.y, tv.y, Q[1]);
            P[2] = fma2_(wB.x, tv.x, P[2]);  Q[2] = fma2_(wB.x, tv.y, Q[2]);
            P[3] = fma2_(wB.y, tv.x, P[3]);  Q[3] = fma2_(wB.y, tv.y, Q[3]);
            P[4] = fma2_(wC,   tv.x, P[4]);  Q[4] = fma2_(wC,   tv.y, Q[4]);
        }
        // merge the two k-halves
        #pragma unroll
        for (int s = 0; s < SW; s++) {
            P[s] = add2(P[s], __shfl_xor_sync(0xffffffffu, P[s], 16));
            Q[s] = add2(Q[s], __shfl_xor_sync(0xffffffffu, Q[s], 16));
        }

        // ---- Euler-Maruyama update: h=0 -> s=0..2, h=1 -> s=3..4 ----
        #pragma unroll
        for (int j = 0; j < 3; j++) {
            int s = h * 3 + j;
            if (s < SW) {
                int cs = min(sbase + s, NB - 1);
                float invS = 1.0f / S[s];
                float2 z = *reinterpret_cast<const float2*>(
                    noise + ((size_t)i * NB + (size_t)cs) * ND + 2*p);
                float2 xo = *reinterpret_cast<float2*>(&sm_x[wid][s][2*p]);
                float pa, pb, qa, qb;
                upk2(P[s], pa, pb);
                upk2(Q[s], qa, qb);
                xo.x = upd1(xo.x, pa, qa, invS, hb, sn, z.x);
                xo.y = upd1(xo.y, pb, qb, invS, hb, sn, z.y);
                *reinterpret_cast<float2*>(&sm_x[wid][s][2*p]) = xo;
            }
        }
        // next-step readers wait at loop-top __syncthreads
    }

    // ---- final store ----
    #pragma unroll
    for (int j = 0; j < 3; j++) {
        int s = h * 3 + j;
        if (s < SW) {
            int r = sbase + s;
            if (r < NB) {
                *reinterpret_cast<float2*>(out + (size_t)r * ND + 2*p) =
                    *reinterpret_cast<const float2*>(&sm_x[wid][s][2*p]);
            }
        }
    }
}

extern "C" void kernel_launch(void* const* d_in, const int* in_sizes, int n_in,
                              void* d_out, int out_size)
{
    const float* x_init  = (const float*)d_in[0];
    const float* centers = (const float*)d_in[1];
    const float* stds    = (const float*)d_in[2];
    const float* weights = (const float*)d_in[3];
    const float* noise   = (const float*)d_in[4];
    float* out = (float*)d_out;

    sbm_kernel<<<NBLK, TPB>>>(x_init, centers, stds, weights, noise, out);
}

// round 11
// speedup vs baseline: 1.9335x; 1.1121x over previous
#include <cuda_runtime.h>
#include <math.h>

#define NB    8192
#define ND    32
#define NK    64
#define NSTEP 255
#define TPB   128        // 4 warps
#define NWRP  4
#define SW    4          // samples per warp
#define SPB   16         // samples per block
#define NBLK  592        // 4 blocks/SM x 148 SMs, uniform; 592*16 = 9472 slots
#define TS4   17         // table row stride in float4
#define WROW  4          // floats per w row (4 samples, 16B)

typedef unsigned long long u64;

__device__ __forceinline__ u64 pk2(float v) {
    u64 r; asm("mov.b64 %0, {%1, %1};" : "=l"(r) : "f"(v)); return r;
}
__device__ __forceinline__ void upk2(u64 v, float& lo, float& hi) {
    asm("mov.b64 {%0, %1}, %2;" : "=f"(lo), "=f"(hi) : "l"(v));
}
__device__ __forceinline__ u64 add2(u64 a, u64 b) {
    u64 d; asm("add.rn.f32x2 %0, %1, %2;" : "=l"(d) : "l"(a), "l"(b)); return d;
}
__device__ __forceinline__ u64 fma2_(u64 a, u64 b, u64 c) {
    u64 d; asm("fma.rn.f32x2 %0, %1, %2, %3;" : "=l"(d) : "l"(a), "l"(b), "l"(c)); return d;
}

__device__ __forceinline__ float upd1(float x, float P, float Q,
                                      float invS, float hb, float sn, float z) {
    // score = (2xP + Q)/S ;  c = 0.5x + score ;  x += hb*c + sn*z
    float tx = x + x;
    float u  = fmaf(tx, P, Q);
    float c  = fmaf(invS, u, 0.5f * x);
    return fmaf(sn, z, fmaf(hb, c, x));
}

__global__ __launch_bounds__(TPB, 4)
void sbm_kernel(const float* __restrict__ x_init,
                const float* __restrict__ centers,
                const float* __restrict__ stds,
                const float* __restrict__ weights,
                const float* __restrict__ noise,
                float* __restrict__ out)
{
    // table row k: 16 chunks (float4) { ivh[2c], ivh[2c+1], am[2c], am[2c+1] }
    // ivh = -0.5/v ; am = m/v
    __shared__ float4 sm_tab[NK * TS4];            // 17408 B
    __shared__ float  sm_c  [NK];                  // 256 B
    __shared__ float  sm_w  [NWRP * NK * WROW];    // 4096 B, rows interleaved (2k+h)
    __shared__ float  sm_x  [NWRP][SW][ND];        // 2048 B

    const int tid  = threadIdx.x;
    const int lane = tid & 31;
    const int wid  = tid >> 5;
    const int p    = lane & 15;        // dim pair (pass 2 / update)
    const int h    = lane >> 4;        // k-half  (pass 2 / update)

    const int sbase = blockIdx.x * SPB + wid * SW;

    // ---- init x slab: lanes cover (pair p) x (samples split by h) ----
    #pragma unroll
    for (int j = 0; j < 2; j++) {
        int s  = h * 2 + j;
        int cs = min(sbase + s, NB - 1);
        *reinterpret_cast<float2*>(&sm_x[wid][s][2*p]) =
            *reinterpret_cast<const float2*>(x_init + (size_t)cs * ND + 2*p);
    }

    const float T_MAX = 1.0f;
    const float T_MIN = 1e-4f;
    const float H   = (T_MAX - T_MIN) / 255.0f;
    const float SQH = sqrtf(H);

    for (int i = 0; i < NSTEP; i++) {
        float t  = T_MAX - (float)i * H;
        float bt = 0.1f + 19.9f * t;
        float Bt = 0.1f * t + 9.95f * t * t;
        float eB = expf(-Bt);
        float om = 1.0f - eB;
        float sq = sqrtf(eB);
        float hb = H * bt;
        float sn = sqrtf(bt) * SQH;

        __syncthreads();   // prev step's table readers done; x slab visible

        // ---- build table: all 128 threads, k = tid/2, half of dims ----
        {
            int k  = tid >> 1;
            int hh = (tid & 1) * 16;
            float lsum = 0.0f, qsum = 0.0f;
            #pragma unroll
            for (int jj = 0; jj < 4; jj++) {
                int d = hh + jj * 4;
                float4 c4 = *reinterpret_cast<const float4*>(centers + k * ND + d);
                float4 s4 = *reinterpret_cast<const float4*>(stds    + k * ND + d);
                float v0 = eB * s4.x * s4.x + om;
                float v1 = eB * s4.y * s4.y + om;
                float v2 = eB * s4.z * s4.z + om;
                float v3 = eB * s4.w * s4.w + om;
                float i0 = 1.0f / v0, i1 = 1.0f / v1, i2 = 1.0f / v2, i3 = 1.0f / v3;
                float m0 = sq * c4.x, m1 = sq * c4.y, m2 = sq * c4.z, m3 = sq * c4.w;
                float a0 = m0 * i0, a1 = m1 * i1, a2 = m2 * i2, a3 = m3 * i3;
                sm_tab[k * TS4 + (d >> 1)    ] = make_float4(-0.5f*i0, -0.5f*i1, a0, a1);
                sm_tab[k * TS4 + (d >> 1) + 1] = make_float4(-0.5f*i2, -0.5f*i3, a2, a3);
                qsum += a0*m0 + a1*m1 + a2*m2 + a3*m3;
                const float TWO_PI = 6.2831853071795864f;
                lsum += __logf(TWO_PI*v0) + __logf(TWO_PI*v1)
                      + __logf(TWO_PI*v2) + __logf(TWO_PI*v3);
            }
            lsum += __shfl_xor_sync(0xffffffffu, lsum, 1);
            qsum += __shfl_xor_sync(0xffffffffu, qsum, 1);
            if ((tid & 1) == 0) {
                sm_c[k] = fmaf(-16.0f, lsum, fmaf(-0.5f, qsum, __logf(weights[k])));
            }
        }
        __syncthreads();

        // ---- pass 1: lane owns k = lane, lane+32; chunk-pair outer ----
        u64 acc0[SW], acc1[SW];
        #pragma unroll
        for (int s = 0; s < SW; s++) { acc0[s] = 0ull; acc1[s] = 0ull; }

        const ulonglong2* t0p = reinterpret_cast<const ulonglong2*>(&sm_tab[lane * TS4]);
        const ulonglong2* t1p = reinterpret_cast<const ulonglong2*>(&sm_tab[(lane + 32) * TS4]);
        #pragma unroll
        for (int c2 = 0; c2 < 8; c2++) {
            ulonglong2 ta0 = t0p[2*c2], ta1 = t0p[2*c2 + 1];
            ulonglong2 tb0 = t1p[2*c2], tb1 = t1p[2*c2 + 1];
            #pragma unroll
            for (int s = 0; s < SW; s++) {
                ulonglong2 xv = *reinterpret_cast<const ulonglong2*>(&sm_x[wid][s][4*c2]);
                acc0[s] = fma2_(fma2_(ta0.x, xv.x, ta0.y), xv.x, acc0[s]);
                acc0[s] = fma2_(fma2_(ta1.x, xv.y, ta1.y), xv.y, acc0[s]);
                acc1[s] = fma2_(fma2_(tb0.x, xv.x, tb0.y), xv.x, acc1[s]);
                acc1[s] = fma2_(fma2_(tb1.x, xv.y, tb1.y), xv.y, acc1[s]);
            }
        }

        // ---- softmax stats (reduce over full warp = 64 k) ----
        float cA = sm_c[lane], cB = sm_c[lane + 32];
        float w0[SW], w1[SW], S[SW];
        #pragma unroll
        for (int s = 0; s < SW; s++) {
            float lo, hi;
            upk2(acc0[s], lo, hi);  float lc0 = (lo + hi) + cA;
            upk2(acc1[s], lo, hi);  float lc1 = (lo + hi) + cB;
            float m = fmaxf(lc0, lc1);
            #pragma unroll
            for (int r = 1; r <= 16; r <<= 1)
                m = fmaxf(m, __shfl_xor_sync(0xffffffffu, m, r));
            float a = __expf(lc0 - m);
            float b = __expf(lc1 - m);
            w0[s] = a; w1[s] = b;
            float ss = a + b;
            #pragma unroll
            for (int r = 1; r <= 16; r <<= 1)
                ss += __shfl_xor_sync(0xffffffffu, ss, r);
            S[s] = ss;
        }

        // ---- store w rows: row 2*lane <- k=lane, row 2*lane+1 <- k=lane+32 ----
        {
            float4* wb = reinterpret_cast<float4*>(
                sm_w + (wid * NK + 2 * lane) * WROW);
            wb[0] = make_float4(w0[0], w0[1], w0[2], w0[3]);
            wb[1] = make_float4(w1[0], w1[1], w1[2], w1[3]);
        }
        __syncwarp();

        // ---- pass 2: lane (p,h) streams k = kk + 32h, P,Q for dim pair p ----
        u64 P[SW], Q[SW];
        #pragma unroll
        for (int s = 0; s < SW; s++) { P[s] = 0ull; Q[s] = 0ull; }

        const float* wbase = sm_w + (wid * NK + h) * WROW;   // row 2kk+h
        #pragma unroll 4
        for (int kk = 0; kk < 32; kk++) {
            ulonglong2 tv = *reinterpret_cast<const ulonglong2*>(
                &sm_tab[(kk + 32 * h) * TS4 + p]);
            float4 w4 = *reinterpret_cast<const float4*>(wbase + kk * (2 * WROW));
            u64 wv0 = pk2(w4.x), wv1 = pk2(w4.y), wv2 = pk2(w4.z), wv3 = pk2(w4.w);
            P[0] = fma2_(wv0, tv.x, P[0]);  Q[0] = fma2_(wv0, tv.y, Q[0]);
            P[1] = fma2_(wv1, tv.x, P[1]);  Q[1] = fma2_(wv1, tv.y, Q[1]);
            P[2] = fma2_(wv2, tv.x, P[2]);  Q[2] = fma2_(wv2, tv.y, Q[2]);
            P[3] = fma2_(wv3, tv.x, P[3]);  Q[3] = fma2_(wv3, tv.y, Q[3]);
        }
        // merge the two k-halves
        #pragma unroll
        for (int s = 0; s < SW; s++) {
            P[s] = add2(P[s], __shfl_xor_sync(0xffffffffu, P[s], 16));
            Q[s] = add2(Q[s], __shfl_xor_sync(0xffffffffu, Q[s], 16));
        }

        // ---- Euler-Maruyama update: h=0 -> s=0,1 ; h=1 -> s=2,3 ----
        #pragma unroll
        for (int j = 0; j < 2; j++) {
            int s  = h * 2 + j;
            int cs = min(sbase + s, NB - 1);
            float invS = 1.0f / S[s];
            float2 z = *reinterpret_cast<const float2*>(
                noise + ((size_t)i * NB + (size_t)cs) * ND + 2*p);
            float2 xo = *reinterpret_cast<float2*>(&sm_x[wid][s][2*p]);
            float pa, pb, qa, qb;
            upk2(P[s], pa, pb);
            upk2(Q[s], qa, qb);
            xo.x = upd1(xo.x, pa, qa, invS, hb, sn, z.x);
            xo.y = upd1(xo.y, pb, qb, invS, hb, sn, z.y);
            *reinterpret_cast<float2*>(&sm_x[wid][s][2*p]) = xo;
        }
        // next-step readers wait at loop-top __syncthreads
    }

    // ---- final store ----
    #pragma unroll
    for (int j = 0; j < 2; j++) {
        int s = h * 2 + j;
        int r = sbase + s;
        if (r < NB) {
            *reinterpret_cast<float2*>(out + (size_t)r * ND + 2*p) =
                *reinterpret_cast<const float2*>(&sm_x[wid][s][2*p]);
        }
    }
}

extern "C" void kernel_launch(void* const* d_in, const int* in_sizes, int n_in,
                              void* d_out, int out_size)
{
    const float* x_init  = (const float*)d_in[0];
    const float* centers = (const float*)d_in[1];
    const float* stds    = (const float*)d_in[2];
    const float* weights = (const float*)d_in[3];
    const float* noise   = (const float*)d_in[4];
    float* out = (float*)d_out;

    sbm_kernel<<<NBLK, TPB>>>(x_init, centers, stds, weights, noise, out);
}